// round 16
// baseline (speedup 1.0000x reference)
#include <cuda_runtime.h>
#include <cuda_bf16.h>
#include <cstdint>

// DotProductAttention B=4,H=8,S=2048,D=16 fp32 — mma.sync (HMMA bf16) flash kernel.
// logits = 10*tanh(QK^T*SCALE); mask(b,key)==1 -> -inf; softmax; O = P@V.
// Fixed softmax max = 10: p = exp2(C2 * rcp(exp2(C1*q.k)+1)).
// bf16 hi/lo exact split for Q,K,P,V; 3 cross terms/GEMM.
// R15: (a) rcp via bit-magic seed + 2 Newton steps (MUFU 3->2 per p; MUFU was the
// binding pipe at ~43us); (b) mask compaction merged into main kernel (smem scan),
// pre-pass kernel deleted (-4.7us -launch). Split-K x2 + reduce kernel kept.

#define S_LEN   2048
#define D_DIM   16
#define H_NUM   8
#define B_NUM   4
#define NQ      65536
#define KT      128
#define THREADS 128
#define SPLIT   2

#define C1_F  1.1047800f       // 2*SCALE*log2(e)
#define C2_F  (-28.85390082f)  // -2*CLIP*log2(e)

// smem strides (bytes): 16B-aligned AND bank-conflict-free for fragment loads
#define KSTRIDE 80
#define VSTRIDE 272

__device__ float g_po[(size_t)SPLIT * NQ * D_DIM];   // 8.4 MB unnormalized partial O
__device__ float g_ps[(size_t)SPLIT * NQ];           // partial row sums

__device__ __forceinline__ float ex2f(float x){ float r; asm("ex2.approx.ftz.f32 %0, %1;":"=f"(r):"f"(x)); return r; }

// p = exp2(C2 / (exp2(d)+1)); reciprocal via magic seed + 2 Newton (FMA pipe),
// freeing the MUFU pipe (2 MUFU/p instead of 3).
__device__ __forceinline__ float pcalc(float d){
    float u = ex2f(d);
    float a = u + 1.0f;
    float x = __int_as_float(0x7EF477D5 - __float_as_int(a));
    x = x * (2.0f - a * x);
    float t = 2.0f - a * x;
    return ex2f((C2_F * x) * t);
}

// split (f0,f1) into packed bf16x2 hi (rn) and bf16x2 lo (rn of residual).
__device__ __forceinline__ void bsplit2(float f0, float f1, uint32_t& hi, uint32_t& lo){
    uint32_t h;
    asm("cvt.rn.bf16x2.f32 %0, %1, %2;" : "=r"(h) : "f"(f1), "f"(f0));
    float fh0 = __uint_as_float(h << 16);
    float fh1 = __uint_as_float(h & 0xffff0000u);
    float l0 = f0 - fh0, l1 = f1 - fh1;
    uint32_t l;
    asm("cvt.rn.bf16x2.f32 %0, %1, %2;" : "=r"(l) : "f"(l1), "f"(l0));
    hi = h; lo = l;
}

__device__ __forceinline__ void mma16816(float* c, const uint32_t* a, uint32_t b0, uint32_t b1){
    asm volatile("mma.sync.aligned.m16n8k16.row.col.f32.bf16.bf16.f32 "
        "{%0,%1,%2,%3}, {%4,%5,%6,%7}, {%8,%9}, {%0,%1,%2,%3};"
        : "+f"(c[0]), "+f"(c[1]), "+f"(c[2]), "+f"(c[3])
        : "r"(a[0]), "r"(a[1]), "r"(a[2]), "r"(a[3]), "r"(b0), "r"(b1));
}

__global__ __launch_bounds__(THREADS, 6)
void attn_mma_kernel(const float* __restrict__ Q, const float* __restrict__ K,
                     const float* __restrict__ V, const int* __restrict__ mask)
{
    __shared__ __align__(16) unsigned char sK[KT * KSTRIDE];   // 10240 B
    __shared__ __align__(16) unsigned char sV[32 * VSTRIDE];   // 8704 B
    __shared__ int sKidx[S_LEN];                                // 8192 B
    __shared__ int sWcnt[68];

    const int tid  = threadIdx.x;
    const int warp = tid >> 5, lane = tid & 31;
    const int g    = lane >> 2, tig = lane & 3;
    const int bh   = blockIdx.y, b = bh >> 3;
    const int z    = blockIdx.z;
    const int qw   = blockIdx.x * THREADS + warp * 32;

    const float* Kb = K + (size_t)bh * S_LEN * D_DIM;
    const float* Vb = V + (size_t)bh * S_LEN * D_DIM;

    // ---- in-kernel mask compaction: ballot-scan 2048 keys into sKidx ----
    {
        const int* Mb = mask + (size_t)b * S_LEN;
        unsigned bals[16];
#pragma unroll
        for (int r = 0; r < 16; r++) {
            bool keep = (Mb[r * 128 + warp * 32 + lane] == 0);
            bals[r] = __ballot_sync(0xffffffffu, keep);
        }
        if (lane == 0) {
#pragma unroll
            for (int r = 0; r < 16; r++) sWcnt[r * 4 + warp] = __popc(bals[r]);
        }
        __syncthreads();
        if (warp == 0) {          // exclusive prefix over 64 counts (2 elems/lane)
            int c0 = sWcnt[lane], c1 = sWcnt[lane + 32];
            int s0 = c0, s1 = c1;
#pragma unroll
            for (int off = 1; off < 32; off <<= 1) {
                int v0 = __shfl_up_sync(0xffffffffu, s0, off);
                int v1 = __shfl_up_sync(0xffffffffu, s1, off);
                if (lane >= off) { s0 += v0; s1 += v1; }
            }
            int tot0 = __shfl_sync(0xffffffffu, s0, 31);
            int tot1 = __shfl_sync(0xffffffffu, s1, 31);
            sWcnt[lane]      = s0 - c0;
            sWcnt[lane + 32] = tot0 + s1 - c1;
            if (lane == 0) sWcnt[64] = tot0 + tot1;
        }
        __syncthreads();
        const unsigned lmask = (1u << lane) - 1u;
#pragma unroll
        for (int r = 0; r < 16; r++) {
            unsigned bal = bals[r];
            if ((bal >> lane) & 1u)
                sKidx[sWcnt[r * 4 + warp] + __popc(bal & lmask)] = r * 128 + warp * 32 + lane;
        }
        __syncthreads();
    }
    const int cnt   = sWcnt[64];
    const int T     = (cnt + KT - 1) / KT;
    const int Th    = (T + 1) >> 1;
    const int t_beg = z * Th;
    const int t_end = z ? T : Th;

    // ---- Q fragments (A of GEMM1), pre-scaled by C1, hi/lo split ----
    uint32_t qh[2][4], ql[2][4];
#pragma unroll
    for (int mb = 0; mb < 2; mb++) {
        const float* q0 = Q + ((size_t)bh * S_LEN + qw + mb * 16 + g) * D_DIM;
        const float* q1 = q0 + 8 * D_DIM;
        float2 f00 = *(const float2*)(q0 + 2 * tig);
        float2 f10 = *(const float2*)(q1 + 2 * tig);
        float2 f01 = *(const float2*)(q0 + 2 * tig + 8);
        float2 f11 = *(const float2*)(q1 + 2 * tig + 8);
        bsplit2(f00.x * C1_F, f00.y * C1_F, qh[mb][0], ql[mb][0]);
        bsplit2(f10.x * C1_F, f10.y * C1_F, qh[mb][1], ql[mb][1]);
        bsplit2(f01.x * C1_F, f01.y * C1_F, qh[mb][2], ql[mb][2]);
        bsplit2(f11.x * C1_F, f11.y * C1_F, qh[mb][3], ql[mb][3]);
    }

    float oc[2][2][4];
#pragma unroll
    for (int mb = 0; mb < 2; mb++)
#pragma unroll
        for (int nd = 0; nd < 2; nd++)
#pragma unroll
            for (int i = 0; i < 4; i++) oc[mb][nd][i] = 0.0f;
    float s00 = 0.f, s01 = 0.f, s10 = 0.f, s11 = 0.f;

    for (int t = t_beg; t < t_end; t++) {
        __syncthreads();
        // ---- load tile: thread owns compacted key slot tid ----
        {
            const int idx = t * KT + tid;
            float kv[16], vv[16];
            if (idx < cnt) {
                const int j = sKidx[idx];
                const float4* kp = (const float4*)(Kb + (size_t)j * D_DIM);
                const float4* vp = (const float4*)(Vb + (size_t)j * D_DIM);
#pragma unroll
                for (int i = 0; i < 4; i++) {
                    float4 tk = kp[i], tv = vp[i];
                    kv[4*i+0]=tk.x; kv[4*i+1]=tk.y; kv[4*i+2]=tk.z; kv[4*i+3]=tk.w;
                    vv[4*i+0]=tv.x; vv[4*i+1]=tv.y; vv[4*i+2]=tv.z; vv[4*i+3]=tv.w;
                }
            } else {
#pragma unroll
                for (int i = 0; i < 16; i++) { kv[i] = 0.f; vv[i] = 0.f; }
            }
            uint32_t khi[8], klo[8];
#pragma unroll
            for (int i = 0; i < 8; i++) bsplit2(kv[2*i], kv[2*i+1], khi[i], klo[i]);
            uint4* kd = (uint4*)(sK + tid * KSTRIDE);
            kd[0] = make_uint4(khi[0], khi[1], khi[2], khi[3]);
            kd[1] = make_uint4(khi[4], khi[5], khi[6], khi[7]);
            kd[2] = make_uint4(klo[0], klo[1], klo[2], klo[3]);
            kd[3] = make_uint4(klo[4], klo[5], klo[6], klo[7]);
#pragma unroll
            for (int d = 0; d < 16; d++) {
                float f = vv[d];
                __nv_bfloat16 h = __float2bfloat16(f);
                float fh = __bfloat162float(h);
                __nv_bfloat16 l = __float2bfloat16(f - fh);
                *(unsigned short*)(sV + d * VSTRIDE + tid * 2)        = __bfloat16_as_ushort(h);
                *(unsigned short*)(sV + (d + 16) * VSTRIDE + tid * 2) = __bfloat16_as_ushort(l);
            }
        }
        __syncthreads();

        const bool full = (t + 1) * KT <= cnt;
        const int  kb0  = t * KT + 2 * tig;

#pragma unroll
        for (int j = 0; j < 8; j++) {
            const unsigned char* ka = sK + (16 * j + g) * KSTRIDE + tig * 4;
            uint32_t kh0a = *(const uint32_t*)(ka);
            uint32_t kh0b = *(const uint32_t*)(ka + 16);
            uint32_t kl0a = *(const uint32_t*)(ka + 32);
            uint32_t kl0b = *(const uint32_t*)(ka + 48);
            uint32_t kh1a = *(const uint32_t*)(ka + 8 * KSTRIDE);
            uint32_t kh1b = *(const uint32_t*)(ka + 8 * KSTRIDE + 16);
            uint32_t kl1a = *(const uint32_t*)(ka + 8 * KSTRIDE + 32);
            uint32_t kl1b = *(const uint32_t*)(ka + 8 * KSTRIDE + 48);

            float c[2][2][4];
#pragma unroll
            for (int mb = 0; mb < 2; mb++) {
#pragma unroll
                for (int nb = 0; nb < 2; nb++)
#pragma unroll
                    for (int i = 0; i < 4; i++) c[mb][nb][i] = 0.0f;
                mma16816(c[mb][0], qh[mb], kh0a, kh0b);
                mma16816(c[mb][0], qh[mb], kl0a, kl0b);
                mma16816(c[mb][0], ql[mb], kh0a, kh0b);
                mma16816(c[mb][1], qh[mb], kh1a, kh1b);
                mma16816(c[mb][1], qh[mb], kl1a, kl1b);
                mma16816(c[mb][1], ql[mb], kh1a, kh1b);
            }

            uint32_t ph[2][4], pl[2][4];
            const int kcol = kb0 + 16 * j;
#pragma unroll
            for (int mb = 0; mb < 2; mb++) {
#pragma unroll
                for (int nb = 0; nb < 2; nb++) {
                    float p0 = pcalc(c[mb][nb][0]);
                    float p1 = pcalc(c[mb][nb][1]);
                    float p2 = pcalc(c[mb][nb][2]);
                    float p3 = pcalc(c[mb][nb][3]);
                    if (!full) {
                        if (kcol + nb * 8     >= cnt) { p0 = 0.f; p2 = 0.f; }
                        if (kcol + nb * 8 + 1 >= cnt) { p1 = 0.f; p3 = 0.f; }
                    }
                    if (mb == 0) { s00 += p0 + p1; s01 += p2 + p3; }
                    else         { s10 += p0 + p1; s11 += p2 + p3; }
                    bsplit2(p0, p1, ph[mb][nb * 2 + 0], pl[mb][nb * 2 + 0]);
                    bsplit2(p2, p3, ph[mb][nb * 2 + 1], pl[mb][nb * 2 + 1]);
                }
            }

            const unsigned char* va = sV + g * VSTRIDE + j * 32 + tig * 4;
            uint32_t vh0a = *(const uint32_t*)(va);
            uint32_t vh0b = *(const uint32_t*)(va + 16);
            uint32_t vh1a = *(const uint32_t*)(va + 8 * VSTRIDE);
            uint32_t vh1b = *(const uint32_t*)(va + 8 * VSTRIDE + 16);
            uint32_t vl0a = *(const uint32_t*)(va + 16 * VSTRIDE);
            uint32_t vl0b = *(const uint32_t*)(va + 16 * VSTRIDE + 16);
            uint32_t vl1a = *(const uint32_t*)(va + 24 * VSTRIDE);
            uint32_t vl1b = *(const uint32_t*)(va + 24 * VSTRIDE + 16);

#pragma unroll
            for (int mb = 0; mb < 2; mb++) {
                mma16816(oc[mb][0], ph[mb], vh0a, vh0b);
                mma16816(oc[mb][0], ph[mb], vl0a, vl0b);
                mma16816(oc[mb][0], pl[mb], vh0a, vh0b);
                mma16816(oc[mb][1], ph[mb], vh1a, vh1b);
                mma16816(oc[mb][1], ph[mb], vl1a, vl1b);
                mma16816(oc[mb][1], pl[mb], vh1a, vh1b);
            }
        }
    }

    // ---- quad-reduce row sums; write unnormalized partials to scratch ----
    s00 += __shfl_xor_sync(0xffffffffu, s00, 1); s00 += __shfl_xor_sync(0xffffffffu, s00, 2);
    s01 += __shfl_xor_sync(0xffffffffu, s01, 1); s01 += __shfl_xor_sync(0xffffffffu, s01, 2);
    s10 += __shfl_xor_sync(0xffffffffu, s10, 1); s10 += __shfl_xor_sync(0xffffffffu, s10, 2);
    s11 += __shfl_xor_sync(0xffffffffu, s11, 1); s11 += __shfl_xor_sync(0xffffffffu, s11, 2);

    const size_t qbase = (size_t)z * NQ + (size_t)bh * S_LEN + qw;
    if (tig == 0) {
        g_ps[qbase + g]      = s00;
        g_ps[qbase + 8 + g]  = s01;
        g_ps[qbase + 16 + g] = s10;
        g_ps[qbase + 24 + g] = s11;
    }
#pragma unroll
    for (int mb = 0; mb < 2; mb++) {
#pragma unroll
        for (int nd = 0; nd < 2; nd++) {
            float* o0 = g_po + (qbase + mb * 16 + g) * D_DIM + nd * 8 + 2 * tig;
            *(float2*)(o0)             = make_float2(oc[mb][nd][0], oc[mb][nd][1]);
            *(float2*)(o0 + 8 * D_DIM) = make_float2(oc[mb][nd][2], oc[mb][nd][3]);
        }
    }
}

__global__ __launch_bounds__(256)
void attn_reduce_kernel(float* __restrict__ O)
{
    const int q = blockIdx.x * 256 + threadIdx.x;
    const float inv = 1.0f / (g_ps[q] + g_ps[NQ + q]);
    const float4* p0 = (const float4*)(g_po + (size_t)q * D_DIM);
    const float4* p1 = (const float4*)(g_po + ((size_t)NQ + q) * D_DIM);
    float4* op = (float4*)(O + (size_t)q * D_DIM);
#pragma unroll
    for (int i = 0; i < 4; i++) {
        float4 a = p0[i], b = p1[i];
        op[i] = make_float4((a.x + b.x) * inv, (a.y + b.y) * inv,
                            (a.z + b.z) * inv, (a.w + b.w) * inv);
    }
}

extern "C" void kernel_launch(void* const* d_in, const int* in_sizes, int n_in,
                              void* d_out, int out_size)
{
    const float* Q = (const float*)d_in[0];
    const float* K = (const float*)d_in[1];
    const float* V = (const float*)d_in[2];
    const int* mask = (const int*)d_in[3];
    float* O = (float*)d_out;

    dim3 grid(S_LEN / THREADS, B_NUM * H_NUM, SPLIT);   // (16, 32, 2)
    attn_mma_kernel<<<grid, THREADS>>>(Q, K, V, mask);
    attn_reduce_kernel<<<NQ / 256, 256>>>(O);
}

// round 17
// speedup vs baseline: 1.1375x; 1.1375x over previous
#include <cuda_runtime.h>
#include <cuda_bf16.h>
#include <cstdint>

// DotProductAttention B=4,H=8,S=2048,D=16 fp32 — mma.sync (HMMA bf16) flash kernel.
// logits = 10*tanh(QK^T*SCALE); mask(b,key)==1 -> -inf; softmax; O = P@V.
// Fixed softmax max = 10: p = exp2(C2 * rcp(exp2(C1*q.k)+1)).
// bf16 hi/lo exact split for Q,K,P,V; 3 cross terms/GEMM. Split-K x2 + reduce.
// R17: revert Newton-rcp (issue-bound, not MUFU-bound: +40% instr was the R16
// regression); keep in-kernel mask compaction; 4x-parallel reduce kernel.

#define S_LEN   2048
#define D_DIM   16
#define H_NUM   8
#define B_NUM   4
#define NQ      65536
#define KT      128
#define THREADS 128
#define SPLIT   2

#define C1_F  1.1047800f       // 2*SCALE*log2(e)
#define C2_F  (-28.85390082f)  // -2*CLIP*log2(e)

// smem strides (bytes): 16B-aligned AND bank-conflict-free for fragment loads
#define KSTRIDE 80
#define VSTRIDE 272

__device__ float g_po[(size_t)SPLIT * NQ * D_DIM];   // 8.4 MB unnormalized partial O
__device__ float g_ps[(size_t)SPLIT * NQ];           // partial row sums

__device__ __forceinline__ float ex2f(float x){ float r; asm("ex2.approx.ftz.f32 %0, %1;":"=f"(r):"f"(x)); return r; }
__device__ __forceinline__ float rcpf(float x){ float r; asm("rcp.approx.ftz.f32 %0, %1;":"=f"(r):"f"(x)); return r; }

// p = exp2(C2 / (exp2(d)+1)) — 3 MUFU, minimal issue count.
__device__ __forceinline__ float pcalc(float d){
    return ex2f(C2_F * rcpf(ex2f(d) + 1.0f));
}

// split (f0,f1) into packed bf16x2 hi (rn) and bf16x2 lo (rn of residual).
__device__ __forceinline__ void bsplit2(float f0, float f1, uint32_t& hi, uint32_t& lo){
    uint32_t h;
    asm("cvt.rn.bf16x2.f32 %0, %1, %2;" : "=r"(h) : "f"(f1), "f"(f0));
    float fh0 = __uint_as_float(h << 16);
    float fh1 = __uint_as_float(h & 0xffff0000u);
    float l0 = f0 - fh0, l1 = f1 - fh1;
    uint32_t l;
    asm("cvt.rn.bf16x2.f32 %0, %1, %2;" : "=r"(l) : "f"(l1), "f"(l0));
    hi = h; lo = l;
}

__device__ __forceinline__ void mma16816(float* c, const uint32_t* a, uint32_t b0, uint32_t b1){
    asm volatile("mma.sync.aligned.m16n8k16.row.col.f32.bf16.bf16.f32 "
        "{%0,%1,%2,%3}, {%4,%5,%6,%7}, {%8,%9}, {%0,%1,%2,%3};"
        : "+f"(c[0]), "+f"(c[1]), "+f"(c[2]), "+f"(c[3])
        : "r"(a[0]), "r"(a[1]), "r"(a[2]), "r"(a[3]), "r"(b0), "r"(b1));
}

__global__ __launch_bounds__(THREADS, 6)
void attn_mma_kernel(const float* __restrict__ Q, const float* __restrict__ K,
                     const float* __restrict__ V, const int* __restrict__ mask)
{
    __shared__ __align__(16) unsigned char sK[KT * KSTRIDE];   // 10240 B
    __shared__ __align__(16) unsigned char sV[32 * VSTRIDE];   // 8704 B
    __shared__ int sKidx[S_LEN];                                // 8192 B
    __shared__ int sWcnt[68];

    const int tid  = threadIdx.x;
    const int warp = tid >> 5, lane = tid & 31;
    const int g    = lane >> 2, tig = lane & 3;
    const int bh   = blockIdx.y, b = bh >> 3;
    const int z    = blockIdx.z;
    const int qw   = blockIdx.x * THREADS + warp * 32;

    const float* Kb = K + (size_t)bh * S_LEN * D_DIM;
    const float* Vb = V + (size_t)bh * S_LEN * D_DIM;

    // ---- in-kernel mask compaction: ballot-scan 2048 keys into sKidx ----
    {
        const int* Mb = mask + (size_t)b * S_LEN;
        unsigned bals[16];
#pragma unroll
        for (int r = 0; r < 16; r++) {
            bool keep = (Mb[r * 128 + warp * 32 + lane] == 0);
            bals[r] = __ballot_sync(0xffffffffu, keep);
        }
        if (lane == 0) {
#pragma unroll
            for (int r = 0; r < 16; r++) sWcnt[r * 4 + warp] = __popc(bals[r]);
        }
        __syncthreads();
        if (warp == 0) {          // exclusive prefix over 64 counts (2 elems/lane)
            int c0 = sWcnt[lane], c1 = sWcnt[lane + 32];
            int s0 = c0, s1 = c1;
#pragma unroll
            for (int off = 1; off < 32; off <<= 1) {
                int v0 = __shfl_up_sync(0xffffffffu, s0, off);
                int v1 = __shfl_up_sync(0xffffffffu, s1, off);
                if (lane >= off) { s0 += v0; s1 += v1; }
            }
            int tot0 = __shfl_sync(0xffffffffu, s0, 31);
            int tot1 = __shfl_sync(0xffffffffu, s1, 31);
            sWcnt[lane]      = s0 - c0;
            sWcnt[lane + 32] = tot0 + s1 - c1;
            if (lane == 0) sWcnt[64] = tot0 + tot1;
        }
        __syncthreads();
        const unsigned lmask = (1u << lane) - 1u;
#pragma unroll
        for (int r = 0; r < 16; r++) {
            unsigned bal = bals[r];
            if ((bal >> lane) & 1u)
                sKidx[sWcnt[r * 4 + warp] + __popc(bal & lmask)] = r * 128 + warp * 32 + lane;
        }
        __syncthreads();
    }
    const int cnt   = sWcnt[64];
    const int T     = (cnt + KT - 1) / KT;
    const int Th    = (T + 1) >> 1;
    const int t_beg = z * Th;
    const int t_end = z ? T : Th;

    // ---- Q fragments (A of GEMM1), pre-scaled by C1, hi/lo split ----
    uint32_t qh[2][4], ql[2][4];
#pragma unroll
    for (int mb = 0; mb < 2; mb++) {
        const float* q0 = Q + ((size_t)bh * S_LEN + qw + mb * 16 + g) * D_DIM;
        const float* q1 = q0 + 8 * D_DIM;
        float2 f00 = *(const float2*)(q0 + 2 * tig);
        float2 f10 = *(const float2*)(q1 + 2 * tig);
        float2 f01 = *(const float2*)(q0 + 2 * tig + 8);
        float2 f11 = *(const float2*)(q1 + 2 * tig + 8);
        bsplit2(f00.x * C1_F, f00.y * C1_F, qh[mb][0], ql[mb][0]);
        bsplit2(f10.x * C1_F, f10.y * C1_F, qh[mb][1], ql[mb][1]);
        bsplit2(f01.x * C1_F, f01.y * C1_F, qh[mb][2], ql[mb][2]);
        bsplit2(f11.x * C1_F, f11.y * C1_F, qh[mb][3], ql[mb][3]);
    }

    float oc[2][2][4];
#pragma unroll
    for (int mb = 0; mb < 2; mb++)
#pragma unroll
        for (int nd = 0; nd < 2; nd++)
#pragma unroll
            for (int i = 0; i < 4; i++) oc[mb][nd][i] = 0.0f;
    float s00 = 0.f, s01 = 0.f, s10 = 0.f, s11 = 0.f;

    for (int t = t_beg; t < t_end; t++) {
        __syncthreads();
        // ---- load tile: thread owns compacted key slot tid ----
        {
            const int idx = t * KT + tid;
            float kv[16], vv[16];
            if (idx < cnt) {
                const int j = sKidx[idx];
                const float4* kp = (const float4*)(Kb + (size_t)j * D_DIM);
                const float4* vp = (const float4*)(Vb + (size_t)j * D_DIM);
#pragma unroll
                for (int i = 0; i < 4; i++) {
                    float4 tk = kp[i], tv = vp[i];
                    kv[4*i+0]=tk.x; kv[4*i+1]=tk.y; kv[4*i+2]=tk.z; kv[4*i+3]=tk.w;
                    vv[4*i+0]=tv.x; vv[4*i+1]=tv.y; vv[4*i+2]=tv.z; vv[4*i+3]=tv.w;
                }
            } else {
#pragma unroll
                for (int i = 0; i < 16; i++) { kv[i] = 0.f; vv[i] = 0.f; }
            }
            uint32_t khi[8], klo[8];
#pragma unroll
            for (int i = 0; i < 8; i++) bsplit2(kv[2*i], kv[2*i+1], khi[i], klo[i]);
            uint4* kd = (uint4*)(sK + tid * KSTRIDE);
            kd[0] = make_uint4(khi[0], khi[1], khi[2], khi[3]);
            kd[1] = make_uint4(khi[4], khi[5], khi[6], khi[7]);
            kd[2] = make_uint4(klo[0], klo[1], klo[2], klo[3]);
            kd[3] = make_uint4(klo[4], klo[5], klo[6], klo[7]);
#pragma unroll
            for (int d = 0; d < 16; d++) {
                float f = vv[d];
                __nv_bfloat16 h = __float2bfloat16(f);
                float fh = __bfloat162float(h);
                __nv_bfloat16 l = __float2bfloat16(f - fh);
                *(unsigned short*)(sV + d * VSTRIDE + tid * 2)        = __bfloat16_as_ushort(h);
                *(unsigned short*)(sV + (d + 16) * VSTRIDE + tid * 2) = __bfloat16_as_ushort(l);
            }
        }
        __syncthreads();

        const bool full = (t + 1) * KT <= cnt;
        const int  kb0  = t * KT + 2 * tig;

#pragma unroll
        for (int j = 0; j < 8; j++) {
            const unsigned char* ka = sK + (16 * j + g) * KSTRIDE + tig * 4;
            uint32_t kh0a = *(const uint32_t*)(ka);
            uint32_t kh0b = *(const uint32_t*)(ka + 16);
            uint32_t kl0a = *(const uint32_t*)(ka + 32);
            uint32_t kl0b = *(const uint32_t*)(ka + 48);
            uint32_t kh1a = *(const uint32_t*)(ka + 8 * KSTRIDE);
            uint32_t kh1b = *(const uint32_t*)(ka + 8 * KSTRIDE + 16);
            uint32_t kl1a = *(const uint32_t*)(ka + 8 * KSTRIDE + 32);
            uint32_t kl1b = *(const uint32_t*)(ka + 8 * KSTRIDE + 48);

            float c[2][2][4];
#pragma unroll
            for (int mb = 0; mb < 2; mb++) {
#pragma unroll
                for (int nb = 0; nb < 2; nb++)
#pragma unroll
                    for (int i = 0; i < 4; i++) c[mb][nb][i] = 0.0f;
                mma16816(c[mb][0], qh[mb], kh0a, kh0b);
                mma16816(c[mb][0], qh[mb], kl0a, kl0b);
                mma16816(c[mb][0], ql[mb], kh0a, kh0b);
                mma16816(c[mb][1], qh[mb], kh1a, kh1b);
                mma16816(c[mb][1], qh[mb], kl1a, kl1b);
                mma16816(c[mb][1], ql[mb], kh1a, kh1b);
            }

            uint32_t ph[2][4], pl[2][4];
            const int kcol = kb0 + 16 * j;
#pragma unroll
            for (int mb = 0; mb < 2; mb++) {
#pragma unroll
                for (int nb = 0; nb < 2; nb++) {
                    float p0 = pcalc(c[mb][nb][0]);
                    float p1 = pcalc(c[mb][nb][1]);
                    float p2 = pcalc(c[mb][nb][2]);
                    float p3 = pcalc(c[mb][nb][3]);
                    if (!full) {
                        if (kcol + nb * 8     >= cnt) { p0 = 0.f; p2 = 0.f; }
                        if (kcol + nb * 8 + 1 >= cnt) { p1 = 0.f; p3 = 0.f; }
                    }
                    if (mb == 0) { s00 += p0 + p1; s01 += p2 + p3; }
                    else         { s10 += p0 + p1; s11 += p2 + p3; }
                    bsplit2(p0, p1, ph[mb][nb * 2 + 0], pl[mb][nb * 2 + 0]);
                    bsplit2(p2, p3, ph[mb][nb * 2 + 1], pl[mb][nb * 2 + 1]);
                }
            }

            const unsigned char* va = sV + g * VSTRIDE + j * 32 + tig * 4;
            uint32_t vh0a = *(const uint32_t*)(va);
            uint32_t vh0b = *(const uint32_t*)(va + 16);
            uint32_t vh1a = *(const uint32_t*)(va + 8 * VSTRIDE);
            uint32_t vh1b = *(const uint32_t*)(va + 8 * VSTRIDE + 16);
            uint32_t vl0a = *(const uint32_t*)(va + 16 * VSTRIDE);
            uint32_t vl0b = *(const uint32_t*)(va + 16 * VSTRIDE + 16);
            uint32_t vl1a = *(const uint32_t*)(va + 24 * VSTRIDE);
            uint32_t vl1b = *(const uint32_t*)(va + 24 * VSTRIDE + 16);

#pragma unroll
            for (int mb = 0; mb < 2; mb++) {
                mma16816(oc[mb][0], ph[mb], vh0a, vh0b);
                mma16816(oc[mb][0], ph[mb], vl0a, vl0b);
                mma16816(oc[mb][0], pl[mb], vh0a, vh0b);
                mma16816(oc[mb][1], ph[mb], vh1a, vh1b);
                mma16816(oc[mb][1], ph[mb], vl1a, vl1b);
                mma16816(oc[mb][1], pl[mb], vh1a, vh1b);
            }
        }
    }

    // ---- quad-reduce row sums; write unnormalized partials to scratch ----
    s00 += __shfl_xor_sync(0xffffffffu, s00, 1); s00 += __shfl_xor_sync(0xffffffffu, s00, 2);
    s01 += __shfl_xor_sync(0xffffffffu, s01, 1); s01 += __shfl_xor_sync(0xffffffffu, s01, 2);
    s10 += __shfl_xor_sync(0xffffffffu, s10, 1); s10 += __shfl_xor_sync(0xffffffffu, s10, 2);
    s11 += __shfl_xor_sync(0xffffffffu, s11, 1); s11 += __shfl_xor_sync(0xffffffffu, s11, 2);

    const size_t qbase = (size_t)z * NQ + (size_t)bh * S_LEN + qw;
    if (tig == 0) {
        g_ps[qbase + g]      = s00;
        g_ps[qbase + 8 + g]  = s01;
        g_ps[qbase + 16 + g] = s10;
        g_ps[qbase + 24 + g] = s11;
    }
#pragma unroll
    for (int mb = 0; mb < 2; mb++) {
#pragma unroll
        for (int nd = 0; nd < 2; nd++) {
            float* o0 = g_po + (qbase + mb * 16 + g) * D_DIM + nd * 8 + 2 * tig;
            *(float2*)(o0)             = make_float2(oc[mb][nd][0], oc[mb][nd][1]);
            *(float2*)(o0 + 8 * D_DIM) = make_float2(oc[mb][nd][2], oc[mb][nd][3]);
        }
    }
}

// 4x-parallel reduce: one float4 of output per thread (262144 threads).
__global__ __launch_bounds__(256)
void attn_reduce_kernel(float* __restrict__ O)
{
    const int idx  = blockIdx.x * 256 + threadIdx.x;   // 0..NQ*4-1
    const int q    = idx >> 2;
    const int part = idx & 3;
    const float inv = 1.0f / (g_ps[q] + g_ps[NQ + q]);
    const float4 a = *(const float4*)(g_po + (size_t)q * D_DIM + part * 4);
    const float4 c = *(const float4*)(g_po + ((size_t)NQ + q) * D_DIM + part * 4);
    *(float4*)(O + (size_t)q * D_DIM + part * 4) =
        make_float4((a.x + c.x) * inv, (a.y + c.y) * inv,
                    (a.z + c.z) * inv, (a.w + c.w) * inv);
}

extern "C" void kernel_launch(void* const* d_in, const int* in_sizes, int n_in,
                              void* d_out, int out_size)
{
    const float* Q = (const float*)d_in[0];
    const float* K = (const float*)d_in[1];
    const float* V = (const float*)d_in[2];
    const int* mask = (const int*)d_in[3];
    float* O = (float*)d_out;

    dim3 grid(S_LEN / THREADS, B_NUM * H_NUM, SPLIT);   // (16, 32, 2)
    attn_mma_kernel<<<grid, THREADS>>>(Q, K, V, mask);
    attn_reduce_kernel<<<NQ * 4 / 256, 256>>>(O);
}